// round 2
// baseline (speedup 1.0000x reference)
#include <cuda_runtime.h>
#include <stdint.h>

#define NUM_CLASSES 10000
#define FEATURE_DIM 2048
#define BATCH 512
#define TPB 256
// ALPHA = 0.5 exactly -> powers of two via ldexpf

__device__ int g_lab[BATCH];          // decoded labels
__device__ int g_cnt[NUM_CLASSES];    // per-class occurrence count

// ---------------------------------------------------------------------------
// Prep: zero loss scalar, zero counts, detect int64-vs-int32 label encoding,
// decode labels, histogram counts. One block, 512 threads.
// ---------------------------------------------------------------------------
__global__ void prep_kernel(const int* __restrict__ labels_words,
                            float* __restrict__ loss_out) {
    __shared__ int s_not64;
    int tid = threadIdx.x;
    if (tid == 0) { s_not64 = 0; loss_out[0] = 0.0f; }
    for (int i = tid; i < NUM_CLASSES; i += BATCH) g_cnt[i] = 0;
    __syncthreads();
    int lo = labels_words[2 * tid];
    int hi = labels_words[2 * tid + 1];
    // int64 hypothesis: every odd word 0, every even word a valid class id.
    if (hi != 0 || lo < 0 || lo >= NUM_CLASSES) s_not64 = 1;   // benign race
    __syncthreads();
    int lab = s_not64 ? labels_words[tid] : lo;
    g_lab[tid] = lab;
    atomicAdd(&g_cnt[lab], 1);
}

// ---------------------------------------------------------------------------
// Main: one block per class row.
// MODE 0: out_centers 16B-aligned          -> pure float4 copy
// MODE 1: out_centers base ≡ 4 (mod 16)    -> peel 3+1 scalars, shifted float4
//                                             stores built via __shfl_up
// MODE 2: anything else                    -> scalar copy (fallback)
// Rows with k>0 matches (<=512 of 10000) use the scalar closed-form EMA:
//   new_c = 2^-k * c + sum_r 2^-(k-r) * f_r   (batch order), ALPHA = 0.5.
// ---------------------------------------------------------------------------
template <int MODE>
__global__ void __launch_bounds__(TPB)
center_kernel(const float* __restrict__ features,
              const float* __restrict__ centers,
              float* __restrict__ out_centers,
              float* __restrict__ loss_out) {
    const int l   = blockIdx.x;
    const int tid = threadIdx.x;

    const float* crow = centers     + (size_t)l * FEATURE_DIM;
    float*       orow = out_centers + (size_t)l * FEATURE_DIM;

    const int k = g_cnt[l];   // uniform load, L2-resident

    if (k == 0) {
        if (MODE == 0) {
            const float4* cq = (const float4*)crow;
            float4*       oq = (float4*)orow;
            #pragma unroll
            for (int s = 0; s < (FEATURE_DIM / 4) / TPB; s++) {
                int j = tid + s * TPB;
                oq[j] = __ldg(cq + j);
            }
        } else if (MODE == 1) {
            // orow address ≡ 4 (mod 16): stores of quads [3+4j .. 6+4j] are
            // 16B-aligned. Quad j needs {crow[3+4j], Q_{j+1}.x, .y, .z} where
            // Q_i is the i-th aligned input quad; crow[3+4j] = Q_j.w comes
            // from the previous lane via shfl (lane 0: one scalar load).
            if (tid < 3)  orow[tid]  = __ldg(crow + tid);
            if (tid == 3) orow[FEATURE_DIM - 1] = __ldg(crow + FEATURE_DIM - 1);
            const float4* cq = (const float4*)crow;   // aligned
            #pragma unroll
            for (int s = 0; s < 2; s++) {
                int  j   = tid + s * TPB;
                bool act = j < (FEATURE_DIM / 4) - 1;            // j in [0,510]
                float4 q = act ? __ldg(cq + j + 1)
                               : make_float4(0.f, 0.f, 0.f, 0.f);
                float pw = __shfl_up_sync(0xffffffffu, q.w, 1);
                if ((tid & 31) == 0 && act) pw = __ldg(crow + 4 * j + 3);
                if (act) {
                    float4 o = make_float4(pw, q.x, q.y, q.z);
                    *(float4*)(orow + 3 + 4 * j) = o;
                }
            }
        } else {
            #pragma unroll
            for (int s = 0; s < FEATURE_DIM / TPB; s++) {
                int c = tid + s * TPB;
                orow[c] = __ldg(crow + c);
            }
        }
        return;
    }

    // ---- rare path: k matched samples for this class ----
    __shared__ int   s_match[BATCH];
    __shared__ float s_w[BATCH];
    __shared__ int   s_cnt;
    __shared__ float s_red[TPB / 32];

    if (tid == 0) s_cnt = 0;
    __syncthreads();
    for (int j = tid; j < BATCH; j += TPB) {
        if (g_lab[j] == l) {
            int p = atomicAdd(&s_cnt, 1);
            s_match[p] = j;
        }
    }
    __syncthreads();

    if (tid == 0) {   // restore batch order; precompute EMA weights
        for (int a = 1; a < k; a++) {
            int v = s_match[a];
            int b = a - 1;
            while (b >= 0 && s_match[b] > v) { s_match[b + 1] = s_match[b]; b--; }
            s_match[b + 1] = v;
        }
        for (int r = 0; r < k; r++) s_w[r] = ldexpf(1.0f, -(k - r));
    }
    __syncthreads();

    const float decay = ldexpf(1.0f, -k);
    float acc = 0.0f;

    #pragma unroll
    for (int s = 0; s < FEATURE_DIM / TPB; s++) {
        int c = tid + s * TPB;
        float cv = __ldg(crow + c);
        float nv = cv * decay;
        for (int r = 0; r < k; r++) {
            float f = __ldg(features + (size_t)s_match[r] * FEATURE_DIM + c);
            nv = fmaf(s_w[r], f, nv);
            float d = f - cv;             // loss uses ORIGINAL center row
            acc = fmaf(d, d, acc);
        }
        orow[c] = nv;
    }

    #pragma unroll
    for (int o = 16; o; o >>= 1) acc += __shfl_xor_sync(0xffffffffu, acc, o);
    if ((tid & 31) == 0) s_red[tid >> 5] = acc;
    __syncthreads();
    if (tid < TPB / 32) {
        acc = s_red[tid];
        #pragma unroll
        for (int o = (TPB / 64); o; o >>= 1)
            acc += __shfl_xor_sync((1u << (TPB / 32)) - 1u, acc, o);
        if (tid == 0)
            atomicAdd(loss_out, acc * (1.0f / ((float)BATCH * (float)FEATURE_DIM)));
    }
}

extern "C" void kernel_launch(void* const* d_in, const int* in_sizes, int n_in,
                              void* d_out, int out_size) {
    const float* features = (const float*)d_in[0];
    const int*   labels_w = (const int*)d_in[1];
    const float* centers  = (const float*)d_in[2];

    float* out = (float*)d_out;
    float* out_centers = out + ((size_t)out_size - (size_t)NUM_CLASSES * FEATURE_DIM);

    prep_kernel<<<1, BATCH>>>(labels_w, out);

    uintptr_t a = (uintptr_t)out_centers;
    if ((a & 15) == 0)
        center_kernel<0><<<NUM_CLASSES, TPB>>>(features, centers, out_centers, out);
    else if ((a & 15) == 4)
        center_kernel<1><<<NUM_CLASSES, TPB>>>(features, centers, out_centers, out);
    else
        center_kernel<2><<<NUM_CLASSES, TPB>>>(features, centers, out_centers, out);
}